// round 15
// baseline (speedup 1.0000x reference)
#include <cuda_runtime.h>
#include <float.h>
#include <cstdint>

#define BB   16
#define NPTS 2048
#define BN   (BB * NPTS)
#define KNN  20
#define PPB  32            // points per edge_pool block
#define EPSBN 1e-5f
#define SLOPE 0.2f
#define NTILE (NPTS / 128)            // 16 row-tiles
#define NPAIR (NTILE * (NTILE + 1) / 2)   // 136 triangular block pairs
#define TKBUF 512

// ---------------- scratch (device globals) ----------------
__device__ float g_dist[(size_t)BB * NPTS * NPTS];   // 268 MB neg-distance matrix
__device__ float g_xx[BN];
__device__ int   g_idx[BN * KNN];
__device__ float g_cat[(size_t)BN * 512];   // x1|x2|x3|x4 slices, row stride 512
__device__ float g_ac[(size_t)BN * 512];    // [A | Cc] per edge layer
__device__ float g_mx[(size_t)BN * 256];
__device__ float g_mn[(size_t)BN * 256];
__device__ float g_wt[4][512 * 128];        // transformed weights per layer [2Cout, Cin]
__device__ double g_sum[512];
__device__ double g_sq[512];
__device__ float g_p5max[BB * 16 * 512];
__device__ float g_p5min[BB * 16 * 512];
__device__ float g_z[BB * 512];

// ---------------- small kernels ----------------

__global__ void k_zero_sums() {
    g_sum[threadIdx.x] = 0.0;
    g_sq[threadIdx.x]  = 0.0;
}

__global__ void k_sqnorm(const float* __restrict__ X, int ld, int C) {
    int i = blockIdx.x * blockDim.x + threadIdx.x;
    if (i >= BN) return;
    const float* row = X + (size_t)i * ld;
    float s = 0.f;
    for (int c = 0; c < C; c++) s += row[c] * row[c];
    g_xx[i] = s;
}

// ---------- 128x128 tile SGEMM core, double-buffered (NT: C=A·B^T) ----------

__device__ __forceinline__ void load_tile_scalar(const float* __restrict__ P, int ld, int K,
                                                 int base_row, int k0,
                                                 float (*S)[128], int tid) {
#pragma unroll
    for (int e = 0; e < 8; e++) {
        int i = tid + e * 256;
        int m = i & 127, kk = i >> 7;
        int gk = k0 + kk;
        S[kk][m] = (gk < K) ? P[(size_t)(base_row + m) * ld + gk] : 0.f;
    }
}

#define ST_TILE(S, r0, r1)                                                     \
    do {                                                                       \
        S[c4 + 0][row] = r0.x; S[c4 + 1][row] = r0.y;                          \
        S[c4 + 2][row] = r0.z; S[c4 + 3][row] = r0.w;                          \
        S[c4 + 0][row + 64] = r1.x; S[c4 + 1][row + 64] = r1.y;                \
        S[c4 + 2][row + 64] = r1.z; S[c4 + 3][row + 64] = r1.w;                \
    } while (0)

#define COMPUTE_SLAB(AS, BS)                                                   \
    _Pragma("unroll")                                                          \
    for (int kk = 0; kk < 16; kk++) {                                          \
        float a[8];                                                            \
        float bv[8];                                                           \
        *(float4*)&a[0]  = *(const float4*)&AS[kk][ty * 8];                    \
        *(float4*)&a[4]  = *(const float4*)&AS[kk][ty * 8 + 4];                \
        *(float4*)&bv[0] = *(const float4*)&BS[kk][tx * 8];                    \
        *(float4*)&bv[4] = *(const float4*)&BS[kk][tx * 8 + 4];                \
        _Pragma("unroll")                                                      \
        for (int u = 0; u < 8; u++)                                            \
            _Pragma("unroll")                                                  \
            for (int v = 0; v < 8; v++) acc[u][v] += a[u] * bv[v];             \
    }

// Variadic: epilogue may contain top-level commas.
#define GEMM_CORE(...)                                                         \
    __shared__ float As[2][16][128];                                           \
    __shared__ float Bs[2][16][128];                                           \
    int tid = threadIdx.x;                                                     \
    int tx = tid & 15, ty = tid >> 4;                                          \
    float acc[8][8] = {};                                                      \
    if ((K & 15) == 0) {                                                       \
        int row = tid >> 2, c4 = (tid & 3) * 4;                                \
        const float* pa0 = A + (size_t)(bm + row) * lda + c4;                  \
        const float* pa1 = A + (size_t)(bm + row + 64) * lda + c4;             \
        const float* pb0 = B + (size_t)(bn + row) * ldb + c4;                  \
        const float* pb1 = B + (size_t)(bn + row + 64) * ldb + c4;             \
        float4 ra0 = *(const float4*)pa0;                                      \
        float4 ra1 = *(const float4*)pa1;                                      \
        float4 rb0 = *(const float4*)pb0;                                      \
        float4 rb1 = *(const float4*)pb1;                                      \
        ST_TILE(As[0], ra0, ra1);                                              \
        ST_TILE(Bs[0], rb0, rb1);                                              \
        __syncthreads();                                                       \
        int buf = 0;                                                           \
        for (int k0 = 0; k0 < K; k0 += 16) {                                   \
            bool nxt = (k0 + 16) < K;                                          \
            if (nxt) {                                                         \
                ra0 = *(const float4*)(pa0 + k0 + 16);                         \
                ra1 = *(const float4*)(pa1 + k0 + 16);                         \
                rb0 = *(const float4*)(pb0 + k0 + 16);                         \
                rb1 = *(const float4*)(pb1 + k0 + 16);                         \
            }                                                                  \
            if (buf == 0) { COMPUTE_SLAB(As[0], Bs[0]); }                      \
            else          { COMPUTE_SLAB(As[1], Bs[1]); }                      \
            if (nxt) {                                                         \
                if (buf == 0) { ST_TILE(As[1], ra0, ra1); ST_TILE(Bs[1], rb0, rb1); } \
                else          { ST_TILE(As[0], ra0, ra1); ST_TILE(Bs[0], rb0, rb1); } \
                __syncthreads();                                               \
                buf ^= 1;                                                      \
            }                                                                  \
        }                                                                      \
    } else {                                                                   \
        for (int k0 = 0; k0 < K; k0 += 16) {                                   \
            load_tile_scalar(A, lda, K, bm, k0, As[0], tid);                   \
            load_tile_scalar(B, ldb, K, bn, k0, Bs[0], tid);                   \
            __syncthreads();                                                   \
            COMPUTE_SLAB(As[0], Bs[0]);                                        \
            __syncthreads();                                                   \
        }                                                                      \
    }                                                                          \
    __VA_ARGS__

// Generic NT GEMM: grid (N/128, M/128), block 256
__global__ __launch_bounds__(256, 2)
void k_gemm128(const float* __restrict__ A, int lda,
               const float* __restrict__ B, int ldb,
               float* __restrict__ Cm, int ldc, int K) {
    int bm = blockIdx.y * 128, bn = blockIdx.x * 128;
    GEMM_CORE({
        for (int u = 0; u < 8; u++) {
            size_t ro = (size_t)(bm + ty * 8 + u) * ldc + bn + tx * 8;
            float4 o0 = make_float4(acc[u][0], acc[u][1], acc[u][2], acc[u][3]);
            float4 o1 = make_float4(acc[u][4], acc[u][5], acc[u][6], acc[u][7]);
            *reinterpret_cast<float4*>(&Cm[ro])     = o0;
            *reinterpret_cast<float4*>(&Cm[ro + 4]) = o1;
        }
    })
}

// Symmetric distance kernel (direct mirrored store); full 16 batches.
__global__ __launch_bounds__(256, 2)
void k_dist_sym(const float* __restrict__ X, int ld, int K) {
    int b = blockIdx.z;
    int t = blockIdx.x;
    int bi = 0;
    while (t >= (NTILE - bi)) { t -= (NTILE - bi); bi++; }
    int bj = bi + t;
    int bm = bi * 128, bn = bj * 128;
    const float* A = X + (size_t)b * NPTS * ld;
    const float* B = A;
    int lda = ld, ldb = ld;
    const float* xxb = g_xx + b * NPTS;
    float* Db = g_dist + (size_t)b * NPTS * NPTS;
    GEMM_CORE({
        float xj[8];
        *(float4*)&xj[0] = *(const float4*)&xxb[bn + tx * 8];
        *(float4*)&xj[4] = *(const float4*)&xxb[bn + tx * 8 + 4];
#pragma unroll
        for (int u = 0; u < 8; u++) {
            float xi = xxb[bm + ty * 8 + u];
#pragma unroll
            for (int v = 0; v < 8; v++)
                acc[u][v] = 2.f * acc[u][v] - xi - xj[v];
        }
#pragma unroll
        for (int u = 0; u < 8; u++) {
            size_t ro = (size_t)(bm + ty * 8 + u) * NPTS + bn + tx * 8;
            *reinterpret_cast<float4*>(&Db[ro])     = make_float4(acc[u][0], acc[u][1], acc[u][2], acc[u][3]);
            *reinterpret_cast<float4*>(&Db[ro + 4]) = make_float4(acc[u][4], acc[u][5], acc[u][6], acc[u][7]);
        }
        if (bi != bj) {
#pragma unroll
            for (int v = 0; v < 8; v++) {
                size_t ro = (size_t)(bn + tx * 8 + v) * NPTS + bm + ty * 8;
                *reinterpret_cast<float4*>(&Db[ro])     = make_float4(acc[0][v], acc[1][v], acc[2][v], acc[3][v]);
                *reinterpret_cast<float4*>(&Db[ro + 4]) = make_float4(acc[4][v], acc[5][v], acc[6][v], acc[7][v]);
            }
        }
    })
}

// Two-pass threshold top-20, one warp per row (reads g_dist).
// Pass loops unrolled x8 for higher memory-level parallelism.
__global__ __launch_bounds__(128)
void k_topk() {
    int warp = threadIdx.x >> 5;
    int gw   = (blockIdx.x * blockDim.x + threadIdx.x) >> 5;
    int lane = threadIdx.x & 31;
    if (gw >= BN) return;
    const float4* row = reinterpret_cast<const float4*>(g_dist + (size_t)gw * NPTS);

    __shared__ float sval[4][TKBUF];
    __shared__ int   sidc[4][TKBUF];

    float m1 = -FLT_MAX, m2 = -FLT_MAX;
#pragma unroll 8
    for (int it = 0; it < NPTS / 128; it++) {
        float4 f = row[lane + it * 32];
        float c[4] = { f.x, f.y, f.z, f.w };
#pragma unroll
        for (int q = 0; q < 4; q++) {
            float d  = c[q];
            float lo = fminf(d, m1);
            m1 = fmaxf(d, m1);
            m2 = fmaxf(m2, lo);
        }
    }
    float thr = -FLT_MAX;
    for (int t = 0; t < KNN; t++) {
        float v = m1;
#pragma unroll
        for (int off = 16; off > 0; off >>= 1)
            v = fmaxf(v, __shfl_xor_sync(0xffffffffu, v, off));
        unsigned b = __ballot_sync(0xffffffffu, m1 == v);
        if (lane == (__ffs(b) - 1)) { m1 = m2; m2 = -FLT_MAX; }
        thr = v;
    }

    int base = 0;
#pragma unroll 8
    for (int it = 0; it < NPTS / 128; it++) {
        float4 f = row[lane + it * 32];
        int jb = (lane + it * 32) * 4;
        float c[4] = { f.x, f.y, f.z, f.w };
#pragma unroll
        for (int q = 0; q < 4; q++) {
            bool keep = (c[q] >= thr);
            unsigned m = __ballot_sync(0xffffffffu, keep);
            if (keep) {
                int pos = base + __popc(m & ((1u << lane) - 1));
                if (pos < TKBUF) { sval[warp][pos] = c[q]; sidc[warp][pos] = jb + q; }
            }
            base += __popc(m);
        }
    }
    int M = base < TKBUF ? base : TKBUF;
    __syncwarp();

    for (int t = 0; t < KNN; t++) {
        float lm = -FLT_MAX; int lp = 0;
        for (int i = lane; i < M; i += 32) {
            float s = sval[warp][i];
            if (s > lm) { lm = s; lp = i; }
        }
#pragma unroll
        for (int off = 16; off > 0; off >>= 1) {
            float ov = __shfl_down_sync(0xffffffffu, lm, off);
            int   op = __shfl_down_sync(0xffffffffu, lp, off);
            if (ov > lm) { lm = ov; lp = op; }
        }
        lp = __shfl_sync(0xffffffffu, lp, 0);
        if (lane == 0) {
            g_idx[gw * KNN + t] = sidc[warp][lp];
            sval[warp][lp] = -FLT_MAX;
        }
        __syncwarp();
    }
}

// Fused kNN for layer 1 (C=3): compute distances on the fly, no g_dist traffic.
__global__ __launch_bounds__(128)
void k_knn3(const float* __restrict__ X) {
    int warp = threadIdx.x >> 5;
    int gw   = (blockIdx.x * blockDim.x + threadIdx.x) >> 5;
    int lane = threadIdx.x & 31;
    if (gw >= BN) return;
    int b = gw / NPTS;
    const float* Xb  = X + (size_t)b * NPTS * 3;
    const float* xxb = g_xx + b * NPTS;

    __shared__ float sval[4][TKBUF];
    __shared__ int   sidc[4][TKBUF];

    float xi0 = X[(size_t)gw * 3];
    float xi1 = X[(size_t)gw * 3 + 1];
    float xi2 = X[(size_t)gw * 3 + 2];
    float xxi = g_xx[gw];

    float m1 = -FLT_MAX, m2 = -FLT_MAX;
#pragma unroll 4
    for (int it = 0; it < NPTS / 32; it++) {
        int j = lane + it * 32;
        float y0 = Xb[j * 3], y1 = Xb[j * 3 + 1], y2 = Xb[j * 3 + 2];
        float dot = xi0 * y0 + xi1 * y1 + xi2 * y2;
        float d = 2.f * dot - xxi - xxb[j];
        float lo = fminf(d, m1);
        m1 = fmaxf(d, m1);
        m2 = fmaxf(m2, lo);
    }
    float thr = -FLT_MAX;
    for (int t = 0; t < KNN; t++) {
        float v = m1;
#pragma unroll
        for (int off = 16; off > 0; off >>= 1)
            v = fmaxf(v, __shfl_xor_sync(0xffffffffu, v, off));
        unsigned bb = __ballot_sync(0xffffffffu, m1 == v);
        if (lane == (__ffs(bb) - 1)) { m1 = m2; m2 = -FLT_MAX; }
        thr = v;
    }

    int base = 0;
#pragma unroll 4
    for (int it = 0; it < NPTS / 32; it++) {
        int j = lane + it * 32;
        float y0 = Xb[j * 3], y1 = Xb[j * 3 + 1], y2 = Xb[j * 3 + 2];
        float dot = xi0 * y0 + xi1 * y1 + xi2 * y2;
        float d = 2.f * dot - xxi - xxb[j];
        bool keep = (d >= thr);
        unsigned m = __ballot_sync(0xffffffffu, keep);
        if (keep) {
            int pos = base + __popc(m & ((1u << lane) - 1));
            if (pos < TKBUF) { sval[warp][pos] = d; sidc[warp][pos] = j; }
        }
        base += __popc(m);
    }
    int M = base < TKBUF ? base : TKBUF;
    __syncwarp();

    for (int t = 0; t < KNN; t++) {
        float lm = -FLT_MAX; int lp = 0;
        for (int i = lane; i < M; i += 32) {
            float s = sval[warp][i];
            if (s > lm) { lm = s; lp = i; }
        }
#pragma unroll
        for (int off = 16; off > 0; off >>= 1) {
            float ov = __shfl_down_sync(0xffffffffu, lm, off);
            int   op = __shfl_down_sync(0xffffffffu, lp, off);
            if (ov > lm) { lm = ov; lp = op; }
        }
        lp = __shfl_sync(0xffffffffu, lp, 0);
        if (lane == 0) {
            g_idx[gw * KNN + t] = sidc[warp][lp];
            sval[warp][lp] = -FLT_MAX;
        }
        __syncwarp();
    }
}

// Fused conv5 GEMM + global pool stats. grid (512/128, BN/128), block 256.
__global__ __launch_bounds__(256, 2)
void k_conv5pool(const float* __restrict__ A, const float* __restrict__ B) {
    int lda = 512, ldb = 512, K = 512;
    int bm = blockIdx.y * 128, bn = blockIdx.x * 128;
    int chunk = blockIdx.y;
    GEMM_CORE({
        float tmax[8];
        float tmin[8];
        float tsum[8];
        float tsq[8];
#pragma unroll
        for (int v = 0; v < 8; v++) {
            tmax[v] = -FLT_MAX;
            tmin[v] = FLT_MAX;
            tsum[v] = 0.f;
            tsq[v]  = 0.f;
        }
#pragma unroll
        for (int u = 0; u < 8; u++)
#pragma unroll
            for (int v = 0; v < 8; v++) {
                float y = acc[u][v];
                tmax[v] = fmaxf(tmax[v], y);
                tmin[v] = fminf(tmin[v], y);
                tsum[v] += y;
                tsq[v]  += y * y;
            }
        __syncthreads();
#pragma unroll
        for (int v = 0; v < 8; v++) {
            As[0][ty][tx * 8 + v] = tmax[v];
            Bs[0][ty][tx * 8 + v] = tmin[v];
            As[1][ty][tx * 8 + v] = tsum[v];
            Bs[1][ty][tx * 8 + v] = tsq[v];
        }
        __syncthreads();
        if (tid < 128) {
            float mx = -FLT_MAX;
            float mn = FLT_MAX;
            float s = 0.f;
            float s2 = 0.f;
#pragma unroll
            for (int r = 0; r < 16; r++) {
                mx = fmaxf(mx, As[0][r][tid]);
                mn = fminf(mn, Bs[0][r][tid]);
                s  += As[1][r][tid];
                s2 += Bs[1][r][tid];
            }
            int c = bn + tid;
            g_p5max[chunk * 512 + c] = mx;
            g_p5min[chunk * 512 + c] = mn;
            atomicAdd(&g_sum[c], (double)s);
            atomicAdd(&g_sq[c], (double)s2);
        }
    })
}

// wt[co] = W_d ; wt[Cout+co] = W_c - W_d
__global__ void k_transform_w(const float* __restrict__ w, float* __restrict__ wt,
                              int Cout, int Cin) {
    int i = blockIdx.x * blockDim.x + threadIdx.x;
    if (i >= Cout * Cin) return;
    int co = i / Cin, ci = i % Cin;
    float wd = w[co * 2 * Cin + ci];
    float wc = w[co * 2 * Cin + Cin + ci];
    wt[co * Cin + ci] = wd;
    wt[(Cout + co) * Cin + ci] = wc - wd;
}

// PPB points per block; thread co loops points; one atomic per thread per array
__global__ void k_edge_pool(const float* __restrict__ AC, int Cout) {
    int p0 = blockIdx.x * PPB;
    int b  = p0 / NPTS;
    const float* ACb = AC + (size_t)b * NPTS * 2 * Cout;
    __shared__ int sidx[PPB * KNN];
    for (int i = threadIdx.x; i < PPB * KNN; i += blockDim.x)
        sidx[i] = g_idx[p0 * KNN + i];
    __syncthreads();
    int co = threadIdx.x;                // blockDim == Cout
    float s = 0.f, s2 = 0.f;
    for (int p = 0; p < PPB; p++) {
        int bn = p0 + p;
        float cc = AC[(size_t)bn * 2 * Cout + Cout + co];
        float vmax = -FLT_MAX, vmin = FLT_MAX;
#pragma unroll
        for (int kk = 0; kk < KNN; kk++) {
            float y = ACb[(size_t)sidx[p * KNN + kk] * 2 * Cout + co] + cc;
            vmax = fmaxf(vmax, y); vmin = fminf(vmin, y);
            s += y; s2 += y * y;
        }
        g_mx[(size_t)bn * Cout + co] = vmax;
        g_mn[(size_t)bn * Cout + co] = vmin;
    }
    atomicAdd(&g_sum[co], (double)s);
    atomicAdd(&g_sq[co], (double)s2);
}

// finalize into g_cat slice (row stride ldo)
__global__ void k_edge_fin(const float* __restrict__ gamma, const float* __restrict__ beta,
                           float* __restrict__ Xout, int ldo, int Cout) {
    int i = blockIdx.x * blockDim.x + threadIdx.x;
    if (i >= BN * Cout) return;
    int co = i % Cout, n = i / Cout;
    double cnt  = (double)BN * (double)KNN;
    double mean = g_sum[co] / cnt;
    double var  = g_sq[co] / cnt - mean * mean;
    float sc    = gamma[co] * rsqrtf((float)var + EPSBN);
    float m     = (sc >= 0.f) ? g_mx[i] : g_mn[i];
    float v     = (m - (float)mean) * sc + beta[co];
    Xout[(size_t)n * ldo + co] = (v > 0.f) ? v : SLOPE * v;
}

__global__ void k_pool5_fin(const float* __restrict__ gamma, const float* __restrict__ beta) {
    int b = blockIdx.x, c = threadIdx.x;
    double cnt  = (double)BN;
    double mean = g_sum[c] / cnt;
    double var  = g_sq[c] / cnt - mean * mean;
    float sc    = gamma[c] * rsqrtf((float)var + EPSBN);
    float mx = -FLT_MAX, mn = FLT_MAX;
    for (int t = 0; t < 16; t++) {
        mx = fmaxf(mx, g_p5max[(b * 16 + t) * 512 + c]);
        mn = fminf(mn, g_p5min[(b * 16 + t) * 512 + c]);
    }
    float m = (sc >= 0.f) ? mx : mn;
    float v = (m - (float)mean) * sc + beta[c];
    g_z[b * 512 + c] = (v > 0.f) ? v : SLOPE * v;
}

__global__ void k_embed(const float* __restrict__ we, float* __restrict__ out) {
    int b = blockIdx.x, f = threadIdx.x;
    const float* z  = g_z + b * 512;
    const float* wr = we + f * 512;
    float s = 0.f;
    for (int c = 0; c < 512; c++) s += z[c] * wr[c];
    out[b * 128 + f] = s;
}

// ---------------- host ----------------

static void edge_tail(const float* Xin, int ldx, int Cin,
                      const float* gamma, const float* beta,
                      int Cout, float* Xout, int ldo, float* wt, float* ac) {
    k_gemm128<<<dim3(2 * Cout / 128, BN / 128), 256>>>(Xin, ldx, wt, Cin,
                                                       ac, 2 * Cout, Cin);
    k_zero_sums<<<1, 512>>>();
    k_edge_pool<<<BN / PPB, Cout>>>(ac, Cout);
    k_edge_fin<<<(BN * Cout + 255) / 256, 256>>>(gamma, beta, Xout, ldo, Cout);
}

extern "C" void kernel_launch(void* const* d_in, const int* in_sizes, int n_in,
                              void* d_out, int out_size) {
    const float* x  = (const float*)d_in[0];
    const float* w1 = (const float*)d_in[1];
    const float* g1 = (const float*)d_in[2];
    const float* b1 = (const float*)d_in[3];
    const float* w2 = (const float*)d_in[4];
    const float* g2 = (const float*)d_in[5];
    const float* b2 = (const float*)d_in[6];
    const float* w3 = (const float*)d_in[7];
    const float* g3 = (const float*)d_in[8];
    const float* b3 = (const float*)d_in[9];
    const float* w4 = (const float*)d_in[10];
    const float* g4 = (const float*)d_in[11];
    const float* b4 = (const float*)d_in[12];
    const float* w5 = (const float*)d_in[13];
    const float* g5 = (const float*)d_in[14];
    const float* b5 = (const float*)d_in[15];
    const float* we = (const float*)d_in[16];
    float* out = (float*)d_out;

    void *p_cat, *p_ac, *p_wt;
    cudaGetSymbolAddress(&p_cat, g_cat);
    cudaGetSymbolAddress(&p_ac, g_ac);
    cudaGetSymbolAddress(&p_wt, g_wt);
    float* cat = (float*)p_cat;
    float* ac  = (float*)p_ac;
    float* wt0 = (float*)p_wt;
    float* wt1 = wt0 + 512 * 128;
    float* wt2 = wt1 + 512 * 128;
    float* wt3 = wt2 + 512 * 128;

    dim3 dsym(NPAIR, 1, BB);

    // ---- layer 1 (fused kNN: no distance matrix) ----
    k_sqnorm<<<BN / 256, 256>>>(x, 3, 3);
    k_transform_w<<<1, 256>>>(w1, wt0, 64, 3);
    k_transform_w<<<(64 * 64 + 255) / 256, 256>>>(w2, wt1, 64, 64);
    k_transform_w<<<(128 * 64 + 255) / 256, 256>>>(w3, wt2, 128, 64);
    k_transform_w<<<(256 * 128 + 255) / 256, 256>>>(w4, wt3, 256, 128);
    k_knn3<<<BN / 4, 128>>>(x);
    edge_tail(x, 3, 3, g1, b1, 64, cat + 0, 512, wt0, ac);

    // ---- layer 2 ----
    k_sqnorm<<<BN / 256, 256>>>(cat + 0, 512, 64);
    k_dist_sym<<<dsym, 256>>>(cat + 0, 512, 64);
    k_topk<<<BN / 4, 128>>>();
    edge_tail(cat + 0, 512, 64, g2, b2, 64, cat + 64, 512, wt1, ac);

    // ---- layer 3 ----
    k_sqnorm<<<BN / 256, 256>>>(cat + 64, 512, 64);
    k_dist_sym<<<dsym, 256>>>(cat + 64, 512, 64);
    k_topk<<<BN / 4, 128>>>();
    edge_tail(cat + 64, 512, 64, g3, b3, 128, cat + 128, 512, wt2, ac);

    // ---- layer 4 ----
    k_sqnorm<<<BN / 256, 256>>>(cat + 128, 512, 128);
    k_dist_sym<<<dsym, 256>>>(cat + 128, 512, 128);
    k_topk<<<BN / 4, 128>>>();
    edge_tail(cat + 128, 512, 128, g4, b4, 256, cat + 256, 512, wt3, ac);

    // ---- conv5 fused with global pool, then finalize + embed ----
    k_zero_sums<<<1, 512>>>();
    k_conv5pool<<<dim3(512 / 128, BN / 128), 256>>>(cat, w5);
    k_pool5_fin<<<BB, 512>>>(g5, b5);
    k_embed<<<BB, 128>>>(we, out);
}

// round 17
// speedup vs baseline: 1.0285x; 1.0285x over previous
#include <cuda_runtime.h>
#include <float.h>
#include <cstdint>

#define BB   16
#define NPTS 2048
#define BN   (BB * NPTS)
#define KNN  20
#define PPB  32            // points per edge_pool block
#define EPSBN 1e-5f
#define SLOPE 0.2f
#define NTILE (NPTS / 128)            // 16 row-tiles
#define NPAIR (NTILE * (NTILE + 1) / 2)   // 136 triangular block pairs
#define TKBUF 512

// ---------------- scratch (device globals) ----------------
__device__ float g_dist[(size_t)BB * NPTS * NPTS];   // 268 MB neg-distance matrix
__device__ float g_xx[BN];
__device__ int   g_idx[BN * KNN];
__device__ float g_cat[(size_t)BN * 512];   // x1|x2|x3|x4 slices, row stride 512
__device__ float g_ac[(size_t)BN * 512];    // [A | Cc] per edge layer
__device__ float g_mx[(size_t)BN * 256];
__device__ float g_mn[(size_t)BN * 256];
__device__ float g_wt[4][512 * 128];        // transformed weights per layer [2Cout, Cin]
__device__ double g_sum[512];
__device__ double g_sq[512];
__device__ float g_p5max[BB * 16 * 512];
__device__ float g_p5min[BB * 16 * 512];
__device__ float g_z[BB * 512];

// ---------------- small kernels ----------------

__global__ void k_zero_sums() {
    g_sum[threadIdx.x] = 0.0;
    g_sq[threadIdx.x]  = 0.0;
}

__global__ void k_sqnorm(const float* __restrict__ X, int ld, int C) {
    int i = blockIdx.x * blockDim.x + threadIdx.x;
    if (i >= BN) return;
    const float* row = X + (size_t)i * ld;
    float s = 0.f;
    for (int c = 0; c < C; c++) s += row[c] * row[c];
    g_xx[i] = s;
}

// ---------- 128x128 tile SGEMM core, double-buffered (NT: C=A·B^T) ----------

__device__ __forceinline__ void load_tile_scalar(const float* __restrict__ P, int ld, int K,
                                                 int base_row, int k0,
                                                 float (*S)[128], int tid) {
#pragma unroll
    for (int e = 0; e < 8; e++) {
        int i = tid + e * 256;
        int m = i & 127, kk = i >> 7;
        int gk = k0 + kk;
        S[kk][m] = (gk < K) ? P[(size_t)(base_row + m) * ld + gk] : 0.f;
    }
}

#define ST_TILE(S, r0, r1)                                                     \
    do {                                                                       \
        S[c4 + 0][row] = r0.x; S[c4 + 1][row] = r0.y;                          \
        S[c4 + 2][row] = r0.z; S[c4 + 3][row] = r0.w;                          \
        S[c4 + 0][row + 64] = r1.x; S[c4 + 1][row + 64] = r1.y;                \
        S[c4 + 2][row + 64] = r1.z; S[c4 + 3][row + 64] = r1.w;                \
    } while (0)

#define COMPUTE_SLAB(AS, BS)                                                   \
    _Pragma("unroll")                                                          \
    for (int kk = 0; kk < 16; kk++) {                                          \
        float a[8];                                                            \
        float bv[8];                                                           \
        *(float4*)&a[0]  = *(const float4*)&AS[kk][ty * 8];                    \
        *(float4*)&a[4]  = *(const float4*)&AS[kk][ty * 8 + 4];                \
        *(float4*)&bv[0] = *(const float4*)&BS[kk][tx * 8];                    \
        *(float4*)&bv[4] = *(const float4*)&BS[kk][tx * 8 + 4];                \
        _Pragma("unroll")                                                      \
        for (int u = 0; u < 8; u++)                                            \
            _Pragma("unroll")                                                  \
            for (int v = 0; v < 8; v++) acc[u][v] += a[u] * bv[v];             \
    }

// Variadic: epilogue may contain top-level commas.
#define GEMM_CORE(...)                                                         \
    __shared__ float As[2][16][128];                                           \
    __shared__ float Bs[2][16][128];                                           \
    int tid = threadIdx.x;                                                     \
    int tx = tid & 15, ty = tid >> 4;                                          \
    float acc[8][8] = {};                                                      \
    if ((K & 15) == 0) {                                                       \
        int row = tid >> 2, c4 = (tid & 3) * 4;                                \
        const float* pa0 = A + (size_t)(bm + row) * lda + c4;                  \
        const float* pa1 = A + (size_t)(bm + row + 64) * lda + c4;             \
        const float* pb0 = B + (size_t)(bn + row) * ldb + c4;                  \
        const float* pb1 = B + (size_t)(bn + row + 64) * ldb + c4;             \
        float4 ra0 = *(const float4*)pa0;                                      \
        float4 ra1 = *(const float4*)pa1;                                      \
        float4 rb0 = *(const float4*)pb0;                                      \
        float4 rb1 = *(const float4*)pb1;                                      \
        ST_TILE(As[0], ra0, ra1);                                              \
        ST_TILE(Bs[0], rb0, rb1);                                              \
        __syncthreads();                                                       \
        int buf = 0;                                                           \
        for (int k0 = 0; k0 < K; k0 += 16) {                                   \
            bool nxt = (k0 + 16) < K;                                          \
            if (nxt) {                                                         \
                ra0 = *(const float4*)(pa0 + k0 + 16);                         \
                ra1 = *(const float4*)(pa1 + k0 + 16);                         \
                rb0 = *(const float4*)(pb0 + k0 + 16);                         \
                rb1 = *(const float4*)(pb1 + k0 + 16);                         \
            }                                                                  \
            if (buf == 0) { COMPUTE_SLAB(As[0], Bs[0]); }                      \
            else          { COMPUTE_SLAB(As[1], Bs[1]); }                      \
            if (nxt) {                                                         \
                if (buf == 0) { ST_TILE(As[1], ra0, ra1); ST_TILE(Bs[1], rb0, rb1); } \
                else          { ST_TILE(As[0], ra0, ra1); ST_TILE(Bs[0], rb0, rb1); } \
                __syncthreads();                                               \
                buf ^= 1;                                                      \
            }                                                                  \
        }                                                                      \
    } else {                                                                   \
        for (int k0 = 0; k0 < K; k0 += 16) {                                   \
            load_tile_scalar(A, lda, K, bm, k0, As[0], tid);                   \
            load_tile_scalar(B, ldb, K, bn, k0, Bs[0], tid);                   \
            __syncthreads();                                                   \
            COMPUTE_SLAB(As[0], Bs[0]);                                        \
            __syncthreads();                                                   \
        }                                                                      \
    }                                                                          \
    __VA_ARGS__

// Generic NT GEMM: grid (N/128, M/128), block 256
__global__ __launch_bounds__(256, 2)
void k_gemm128(const float* __restrict__ A, int lda,
               const float* __restrict__ B, int ldb,
               float* __restrict__ Cm, int ldc, int K) {
    int bm = blockIdx.y * 128, bn = blockIdx.x * 128;
    GEMM_CORE({
        for (int u = 0; u < 8; u++) {
            size_t ro = (size_t)(bm + ty * 8 + u) * ldc + bn + tx * 8;
            float4 o0 = make_float4(acc[u][0], acc[u][1], acc[u][2], acc[u][3]);
            float4 o1 = make_float4(acc[u][4], acc[u][5], acc[u][6], acc[u][7]);
            *reinterpret_cast<float4*>(&Cm[ro])     = o0;
            *reinterpret_cast<float4*>(&Cm[ro + 4]) = o1;
        }
    })
}

// Symmetric distance kernel (direct mirrored store); full 16 batches.
__global__ __launch_bounds__(256, 2)
void k_dist_sym(const float* __restrict__ X, int ld, int K) {
    int b = blockIdx.z;
    int t = blockIdx.x;
    int bi = 0;
    while (t >= (NTILE - bi)) { t -= (NTILE - bi); bi++; }
    int bj = bi + t;
    int bm = bi * 128, bn = bj * 128;
    const float* A = X + (size_t)b * NPTS * ld;
    const float* B = A;
    int lda = ld, ldb = ld;
    const float* xxb = g_xx + b * NPTS;
    float* Db = g_dist + (size_t)b * NPTS * NPTS;
    GEMM_CORE({
        float xj[8];
        *(float4*)&xj[0] = *(const float4*)&xxb[bn + tx * 8];
        *(float4*)&xj[4] = *(const float4*)&xxb[bn + tx * 8 + 4];
#pragma unroll
        for (int u = 0; u < 8; u++) {
            float xi = xxb[bm + ty * 8 + u];
#pragma unroll
            for (int v = 0; v < 8; v++)
                acc[u][v] = 2.f * acc[u][v] - xi - xj[v];
        }
#pragma unroll
        for (int u = 0; u < 8; u++) {
            size_t ro = (size_t)(bm + ty * 8 + u) * NPTS + bn + tx * 8;
            *reinterpret_cast<float4*>(&Db[ro])     = make_float4(acc[u][0], acc[u][1], acc[u][2], acc[u][3]);
            *reinterpret_cast<float4*>(&Db[ro + 4]) = make_float4(acc[u][4], acc[u][5], acc[u][6], acc[u][7]);
        }
        if (bi != bj) {
#pragma unroll
            for (int v = 0; v < 8; v++) {
                size_t ro = (size_t)(bn + tx * 8 + v) * NPTS + bm + ty * 8;
                *reinterpret_cast<float4*>(&Db[ro])     = make_float4(acc[0][v], acc[1][v], acc[2][v], acc[3][v]);
                *reinterpret_cast<float4*>(&Db[ro + 4]) = make_float4(acc[4][v], acc[5][v], acc[6][v], acc[7][v]);
            }
        }
    })
}

// Two-pass threshold top-20, one warp per row (reads g_dist).
__global__ __launch_bounds__(128)
void k_topk() {
    int warp = threadIdx.x >> 5;
    int gw   = (blockIdx.x * blockDim.x + threadIdx.x) >> 5;
    int lane = threadIdx.x & 31;
    if (gw >= BN) return;
    const float4* row = reinterpret_cast<const float4*>(g_dist + (size_t)gw * NPTS);

    __shared__ float sval[4][TKBUF];
    __shared__ int   sidc[4][TKBUF];

    float m1 = -FLT_MAX, m2 = -FLT_MAX;
#pragma unroll 4
    for (int it = 0; it < NPTS / 128; it++) {
        float4 f = row[lane + it * 32];
        float c[4] = { f.x, f.y, f.z, f.w };
#pragma unroll
        for (int q = 0; q < 4; q++) {
            float d  = c[q];
            float lo = fminf(d, m1);
            m1 = fmaxf(d, m1);
            m2 = fmaxf(m2, lo);
        }
    }
    float thr = -FLT_MAX;
    for (int t = 0; t < KNN; t++) {
        float v = m1;
#pragma unroll
        for (int off = 16; off > 0; off >>= 1)
            v = fmaxf(v, __shfl_xor_sync(0xffffffffu, v, off));
        unsigned b = __ballot_sync(0xffffffffu, m1 == v);
        if (lane == (__ffs(b) - 1)) { m1 = m2; m2 = -FLT_MAX; }
        thr = v;
    }

    int base = 0;
#pragma unroll 4
    for (int it = 0; it < NPTS / 128; it++) {
        float4 f = row[lane + it * 32];
        int jb = (lane + it * 32) * 4;
        float c[4] = { f.x, f.y, f.z, f.w };
#pragma unroll
        for (int q = 0; q < 4; q++) {
            bool keep = (c[q] >= thr);
            unsigned m = __ballot_sync(0xffffffffu, keep);
            if (keep) {
                int pos = base + __popc(m & ((1u << lane) - 1));
                if (pos < TKBUF) { sval[warp][pos] = c[q]; sidc[warp][pos] = jb + q; }
            }
            base += __popc(m);
        }
    }
    int M = base < TKBUF ? base : TKBUF;
    __syncwarp();

    for (int t = 0; t < KNN; t++) {
        float lm = -FLT_MAX; int lp = 0;
        for (int i = lane; i < M; i += 32) {
            float s = sval[warp][i];
            if (s > lm) { lm = s; lp = i; }
        }
#pragma unroll
        for (int off = 16; off > 0; off >>= 1) {
            float ov = __shfl_down_sync(0xffffffffu, lm, off);
            int   op = __shfl_down_sync(0xffffffffu, lp, off);
            if (ov > lm) { lm = ov; lp = op; }
        }
        lp = __shfl_sync(0xffffffffu, lp, 0);
        if (lane == 0) {
            g_idx[gw * KNN + t] = sidc[warp][lp];
            sval[warp][lp] = -FLT_MAX;
        }
        __syncwarp();
    }
}

// Fused kNN for layer 1 (C=3): compute distances on the fly, no g_dist traffic.
__global__ __launch_bounds__(128)
void k_knn3(const float* __restrict__ X) {
    int warp = threadIdx.x >> 5;
    int gw   = (blockIdx.x * blockDim.x + threadIdx.x) >> 5;
    int lane = threadIdx.x & 31;
    if (gw >= BN) return;
    int b = gw / NPTS;
    const float* Xb  = X + (size_t)b * NPTS * 3;
    const float* xxb = g_xx + b * NPTS;

    __shared__ float sval[4][TKBUF];
    __shared__ int   sidc[4][TKBUF];

    float xi0 = X[(size_t)gw * 3];
    float xi1 = X[(size_t)gw * 3 + 1];
    float xi2 = X[(size_t)gw * 3 + 2];
    float xxi = g_xx[gw];

    float m1 = -FLT_MAX, m2 = -FLT_MAX;
#pragma unroll 4
    for (int it = 0; it < NPTS / 32; it++) {
        int j = lane + it * 32;
        float y0 = Xb[j * 3], y1 = Xb[j * 3 + 1], y2 = Xb[j * 3 + 2];
        float dot = xi0 * y0 + xi1 * y1 + xi2 * y2;
        float d = 2.f * dot - xxi - xxb[j];
        float lo = fminf(d, m1);
        m1 = fmaxf(d, m1);
        m2 = fmaxf(m2, lo);
    }
    float thr = -FLT_MAX;
    for (int t = 0; t < KNN; t++) {
        float v = m1;
#pragma unroll
        for (int off = 16; off > 0; off >>= 1)
            v = fmaxf(v, __shfl_xor_sync(0xffffffffu, v, off));
        unsigned bb = __ballot_sync(0xffffffffu, m1 == v);
        if (lane == (__ffs(bb) - 1)) { m1 = m2; m2 = -FLT_MAX; }
        thr = v;
    }

    int base = 0;
#pragma unroll 4
    for (int it = 0; it < NPTS / 32; it++) {
        int j = lane + it * 32;
        float y0 = Xb[j * 3], y1 = Xb[j * 3 + 1], y2 = Xb[j * 3 + 2];
        float dot = xi0 * y0 + xi1 * y1 + xi2 * y2;
        float d = 2.f * dot - xxi - xxb[j];
        bool keep = (d >= thr);
        unsigned m = __ballot_sync(0xffffffffu, keep);
        if (keep) {
            int pos = base + __popc(m & ((1u << lane) - 1));
            if (pos < TKBUF) { sval[warp][pos] = d; sidc[warp][pos] = j; }
        }
        base += __popc(m);
    }
    int M = base < TKBUF ? base : TKBUF;
    __syncwarp();

    for (int t = 0; t < KNN; t++) {
        float lm = -FLT_MAX; int lp = 0;
        for (int i = lane; i < M; i += 32) {
            float s = sval[warp][i];
            if (s > lm) { lm = s; lp = i; }
        }
#pragma unroll
        for (int off = 16; off > 0; off >>= 1) {
            float ov = __shfl_down_sync(0xffffffffu, lm, off);
            int   op = __shfl_down_sync(0xffffffffu, lp, off);
            if (ov > lm) { lm = ov; lp = op; }
        }
        lp = __shfl_sync(0xffffffffu, lp, 0);
        if (lane == 0) {
            g_idx[gw * KNN + t] = sidc[warp][lp];
            sval[warp][lp] = -FLT_MAX;
        }
        __syncwarp();
    }
}

// ---------------- tensor-core conv5 + pool (3xTF32 mma) ----------------

__device__ __forceinline__ uint32_t f2tf(float x) {
    uint32_t r;
    asm("cvt.rna.tf32.f32 %0, %1;\n" : "=r"(r) : "f"(x));
    return r;
}

__device__ __forceinline__ void mma_tf32(float* d,
                                         uint32_t a0, uint32_t a1, uint32_t a2, uint32_t a3,
                                         uint32_t b0, uint32_t b1) {
    asm volatile(
        "mma.sync.aligned.m16n8k8.row.col.f32.tf32.tf32.f32 "
        "{%0,%1,%2,%3}, {%4,%5,%6,%7}, {%8,%9}, {%0,%1,%2,%3};\n"
        : "+f"(d[0]), "+f"(d[1]), "+f"(d[2]), "+f"(d[3])
        : "r"(a0), "r"(a1), "r"(a2), "r"(a3), "r"(b0), "r"(b1));
}

// CTA: 128 rows x 64 cols; 8 warps = 4(M) x 2(N); warp: 32x32 = 2x4 m16n8 tiles.
// grid (512/64 = 8, BN/128 = 256), block 256.
__global__ __launch_bounds__(256, 2)
void k_conv5mma(const float* __restrict__ A, const float* __restrict__ B) {
    __shared__ float sA[128][20];            // 16 k-floats + pad to 20
    __shared__ float sB[64][20];
    __shared__ float rmx[64][4], rmn[64][4], rsm[64][4], rsq[64][4];

    int tid = threadIdx.x;
    int wid = tid >> 5, lane = tid & 31;
    int warpM = wid & 3, warpN = wid >> 2;   // 4 x 2
    int g = lane >> 2, tig = lane & 3;
    int bm = blockIdx.y * 128;
    int bn = blockIdx.x * 64;
    int chunk = blockIdx.y;

    float acc[2][4][4];
#pragma unroll
    for (int i = 0; i < 2; i++)
#pragma unroll
        for (int j = 0; j < 4; j++)
#pragma unroll
            for (int r = 0; r < 4; r++) acc[i][j][r] = 0.f;

    for (int k0 = 0; k0 < 512; k0 += 16) {
        // load A tile 128x16 (512 float4, 2 per thread)
#pragma unroll
        for (int e = 0; e < 2; e++) {
            int ii = tid + e * 256;
            int r = ii >> 2, q = (ii & 3) * 4;
            float4 v = *(const float4*)&A[(size_t)(bm + r) * 512 + k0 + q];
            *(float4*)&sA[r][q] = v;
        }
        // load B tile 64x16 (256 float4, 1 per thread)
        {
            int r = tid >> 2, q = (tid & 3) * 4;
            float4 v = *(const float4*)&B[(size_t)(bn + r) * 512 + k0 + q];
            *(float4*)&sB[r][q] = v;
        }
        __syncthreads();

#pragma unroll
        for (int ks = 0; ks < 16; ks += 8) {
            uint32_t ah[2][4], al[2][4];
#pragma unroll
            for (int mt = 0; mt < 2; mt++) {
                int r0 = warpM * 32 + mt * 16 + g;
                float x0 = sA[r0][ks + tig];
                float x1 = sA[r0 + 8][ks + tig];
                float x2 = sA[r0][ks + tig + 4];
                float x3 = sA[r0 + 8][ks + tig + 4];
                ah[mt][0] = f2tf(x0); al[mt][0] = f2tf(x0 - __uint_as_float(ah[mt][0]));
                ah[mt][1] = f2tf(x1); al[mt][1] = f2tf(x1 - __uint_as_float(ah[mt][1]));
                ah[mt][2] = f2tf(x2); al[mt][2] = f2tf(x2 - __uint_as_float(ah[mt][2]));
                ah[mt][3] = f2tf(x3); al[mt][3] = f2tf(x3 - __uint_as_float(ah[mt][3]));
            }
            uint32_t bh[4][2], bl[4][2];
#pragma unroll
            for (int nt = 0; nt < 4; nt++) {
                int n = warpN * 32 + nt * 8 + g;
                float y0 = sB[n][ks + tig];
                float y1 = sB[n][ks + tig + 4];
                bh[nt][0] = f2tf(y0); bl[nt][0] = f2tf(y0 - __uint_as_float(bh[nt][0]));
                bh[nt][1] = f2tf(y1); bl[nt][1] = f2tf(y1 - __uint_as_float(bh[nt][1]));
            }
#pragma unroll
            for (int mt = 0; mt < 2; mt++)
#pragma unroll
                for (int nt = 0; nt < 4; nt++) {
                    mma_tf32(acc[mt][nt], ah[mt][0], ah[mt][1], ah[mt][2], ah[mt][3],
                             bh[nt][0], bh[nt][1]);
                    mma_tf32(acc[mt][nt], ah[mt][0], ah[mt][1], ah[mt][2], ah[mt][3],
                             bl[nt][0], bl[nt][1]);
                    mma_tf32(acc[mt][nt], al[mt][0], al[mt][1], al[mt][2], al[mt][3],
                             bh[nt][0], bh[nt][1]);
                }
        }
        __syncthreads();
    }

    // ---- epilogue: per-column max/min/sum/sumsq over the CTA's 128 rows ----
    // C frag layout: reg0 (row g,  col 2*tig), reg1 (g, 2*tig+1),
    //                reg2 (g+8, 2*tig), reg3 (g+8, 2*tig+1).
#pragma unroll
    for (int nt = 0; nt < 4; nt++) {
#pragma unroll
        for (int s = 0; s < 2; s++) {
            float v0 = acc[0][nt][s];
            float v1 = acc[0][nt][s + 2];
            float v2 = acc[1][nt][s];
            float v3 = acc[1][nt][s + 2];
            float mx = fmaxf(fmaxf(v0, v1), fmaxf(v2, v3));
            float mn = fminf(fminf(v0, v1), fminf(v2, v3));
            float sm = v0 + v1 + v2 + v3;
            float sq = v0 * v0 + v1 * v1 + v2 * v2 + v3 * v3;
#pragma unroll
            for (int off = 16; off >= 4; off >>= 1) {
                mx = fmaxf(mx, __shfl_down_sync(0xffffffffu, mx, off));
                mn = fminf(mn, __shfl_down_sync(0xffffffffu, mn, off));
                sm += __shfl_down_sync(0xffffffffu, sm, off);
                sq += __shfl_down_sync(0xffffffffu, sq, off);
            }
            if (lane < 4) {
                int col = warpN * 32 + nt * 8 + lane * 2 + s;
                rmx[col][warpM] = mx;
                rmn[col][warpM] = mn;
                rsm[col][warpM] = sm;
                rsq[col][warpM] = sq;
            }
        }
    }
    __syncthreads();
    if (tid < 64) {
        float mx = rmx[tid][0], mn = rmn[tid][0];
        float sm = rsm[tid][0], sq = rsq[tid][0];
#pragma unroll
        for (int r = 1; r < 4; r++) {
            mx = fmaxf(mx, rmx[tid][r]);
            mn = fminf(mn, rmn[tid][r]);
            sm += rsm[tid][r];
            sq += rsq[tid][r];
        }
        int c = bn + tid;
        g_p5max[chunk * 512 + c] = mx;
        g_p5min[chunk * 512 + c] = mn;
        atomicAdd(&g_sum[c], (double)sm);
        atomicAdd(&g_sq[c], (double)sq);
    }
}

// wt[co] = W_d ; wt[Cout+co] = W_c - W_d
__global__ void k_transform_w(const float* __restrict__ w, float* __restrict__ wt,
                              int Cout, int Cin) {
    int i = blockIdx.x * blockDim.x + threadIdx.x;
    if (i >= Cout * Cin) return;
    int co = i / Cin, ci = i % Cin;
    float wd = w[co * 2 * Cin + ci];
    float wc = w[co * 2 * Cin + Cin + ci];
    wt[co * Cin + ci] = wd;
    wt[(Cout + co) * Cin + ci] = wc - wd;
}

// PPB points per block; thread co loops points; one atomic per thread per array
__global__ void k_edge_pool(const float* __restrict__ AC, int Cout) {
    int p0 = blockIdx.x * PPB;
    int b  = p0 / NPTS;
    const float* ACb = AC + (size_t)b * NPTS * 2 * Cout;
    __shared__ int sidx[PPB * KNN];
    for (int i = threadIdx.x; i < PPB * KNN; i += blockDim.x)
        sidx[i] = g_idx[p0 * KNN + i];
    __syncthreads();
    int co = threadIdx.x;                // blockDim == Cout
    float s = 0.f, s2 = 0.f;
    for (int p = 0; p < PPB; p++) {
        int bn = p0 + p;
        float cc = AC[(size_t)bn * 2 * Cout + Cout + co];
        float vmax = -FLT_MAX, vmin = FLT_MAX;
#pragma unroll
        for (int kk = 0; kk < KNN; kk++) {
            float y = ACb[(size_t)sidx[p * KNN + kk] * 2 * Cout + co] + cc;
            vmax = fmaxf(vmax, y); vmin = fminf(vmin, y);
            s += y; s2 += y * y;
        }
        g_mx[(size_t)bn * Cout + co] = vmax;
        g_mn[(size_t)bn * Cout + co] = vmin;
    }
    atomicAdd(&g_sum[co], (double)s);
    atomicAdd(&g_sq[co], (double)s2);
}

// finalize into g_cat slice (row stride ldo)
__global__ void k_edge_fin(const float* __restrict__ gamma, const float* __restrict__ beta,
                           float* __restrict__ Xout, int ldo, int Cout) {
    int i = blockIdx.x * blockDim.x + threadIdx.x;
    if (i >= BN * Cout) return;
    int co = i % Cout, n = i / Cout;
    double cnt  = (double)BN * (double)KNN;
    double mean = g_sum[co] / cnt;
    double var  = g_sq[co] / cnt - mean * mean;
    float sc    = gamma[co] * rsqrtf((float)var + EPSBN);
    float m     = (sc >= 0.f) ? g_mx[i] : g_mn[i];
    float v     = (m - (float)mean) * sc + beta[co];
    Xout[(size_t)n * ldo + co] = (v > 0.f) ? v : SLOPE * v;
}

__global__ void k_pool5_fin(const float* __restrict__ gamma, const float* __restrict__ beta) {
    int b = blockIdx.x, c = threadIdx.x;
    double cnt  = (double)BN;
    double mean = g_sum[c] / cnt;
    double var  = g_sq[c] / cnt - mean * mean;
    float sc    = gamma[c] * rsqrtf((float)var + EPSBN);
    float mx = -FLT_MAX, mn = FLT_MAX;
    for (int t = 0; t < 16; t++) {
        mx = fmaxf(mx, g_p5max[(b * 16 + t) * 512 + c]);
        mn = fminf(mn, g_p5min[(b * 16 + t) * 512 + c]);
    }
    float m = (sc >= 0.f) ? mx : mn;
    float v = (m - (float)mean) * sc + beta[c];
    g_z[b * 512 + c] = (v > 0.f) ? v : SLOPE * v;
}

__global__ void k_embed(const float* __restrict__ we, float* __restrict__ out) {
    int b = blockIdx.x, f = threadIdx.x;
    const float* z  = g_z + b * 512;
    const float* wr = we + f * 512;
    float s = 0.f;
    for (int c = 0; c < 512; c++) s += z[c] * wr[c];
    out[b * 128 + f] = s;
}

// ---------------- host ----------------

static void edge_tail(const float* Xin, int ldx, int Cin,
                      const float* gamma, const float* beta,
                      int Cout, float* Xout, int ldo, float* wt, float* ac) {
    k_gemm128<<<dim3(2 * Cout / 128, BN / 128), 256>>>(Xin, ldx, wt, Cin,
                                                       ac, 2 * Cout, Cin);
    k_zero_sums<<<1, 512>>>();
    k_edge_pool<<<BN / PPB, Cout>>>(ac, Cout);
    k_edge_fin<<<(BN * Cout + 255) / 256, 256>>>(gamma, beta, Xout, ldo, Cout);
}

extern "C" void kernel_launch(void* const* d_in, const int* in_sizes, int n_in,
                              void* d_out, int out_size) {
    const float* x  = (const float*)d_in[0];
    const float* w1 = (const float*)d_in[1];
    const float* g1 = (const float*)d_in[2];
    const float* b1 = (const float*)d_in[3];
    const float* w2 = (const float*)d_in[4];
    const float* g2 = (const float*)d_in[5];
    const float* b2 = (const float*)d_in[6];
    const float* w3 = (const float*)d_in[7];
    const float* g3 = (const float*)d_in[8];
    const float* b3 = (const float*)d_in[9];
    const float* w4 = (const float*)d_in[10];
    const float* g4 = (const float*)d_in[11];
    const float* b4 = (const float*)d_in[12];
    const float* w5 = (const float*)d_in[13];
    const float* g5 = (const float*)d_in[14];
    const float* b5 = (const float*)d_in[15];
    const float* we = (const float*)d_in[16];
    float* out = (float*)d_out;

    void *p_cat, *p_ac, *p_wt;
    cudaGetSymbolAddress(&p_cat, g_cat);
    cudaGetSymbolAddress(&p_ac, g_ac);
    cudaGetSymbolAddress(&p_wt, g_wt);
    float* cat = (float*)p_cat;
    float* ac  = (float*)p_ac;
    float* wt0 = (float*)p_wt;
    float* wt1 = wt0 + 512 * 128;
    float* wt2 = wt1 + 512 * 128;
    float* wt3 = wt2 + 512 * 128;

    dim3 dsym(NPAIR, 1, BB);

    // ---- layer 1 (fused kNN; knn3 at launch index 3 for profiling) ----
    k_sqnorm<<<BN / 256, 256>>>(x, 3, 3);
    k_transform_w<<<1, 256>>>(w1, wt0, 64, 3);
    k_transform_w<<<(64 * 64 + 255) / 256, 256>>>(w2, wt1, 64, 64);
    k_knn3<<<BN / 4, 128>>>(x);
    k_transform_w<<<(128 * 64 + 255) / 256, 256>>>(w3, wt2, 128, 64);
    k_transform_w<<<(256 * 128 + 255) / 256, 256>>>(w4, wt3, 256, 128);
    edge_tail(x, 3, 3, g1, b1, 64, cat + 0, 512, wt0, ac);

    // ---- layer 2 ----
    k_sqnorm<<<BN / 256, 256>>>(cat + 0, 512, 64);
    k_dist_sym<<<dsym, 256>>>(cat + 0, 512, 64);
    k_topk<<<BN / 4, 128>>>();
    edge_tail(cat + 0, 512, 64, g2, b2, 64, cat + 64, 512, wt1, ac);

    // ---- layer 3 ----
    k_sqnorm<<<BN / 256, 256>>>(cat + 64, 512, 64);
    k_dist_sym<<<dsym, 256>>>(cat + 64, 512, 64);
    k_topk<<<BN / 4, 128>>>();
    edge_tail(cat + 64, 512, 64, g3, b3, 128, cat + 128, 512, wt2, ac);

    // ---- layer 4 ----
    k_sqnorm<<<BN / 256, 256>>>(cat + 128, 512, 128);
    k_dist_sym<<<dsym, 256>>>(cat + 128, 512, 128);
    k_topk<<<BN / 4, 128>>>();
    edge_tail(cat + 128, 512, 128, g4, b4, 256, cat + 256, 512, wt3, ac);

    // ---- conv5 via 3xTF32 tensor-core mma, fused with global pool ----
    k_zero_sums<<<1, 512>>>();
    k_conv5mma<<<dim3(8, 256), 256>>>(cat, w5);
    k_pool5_fin<<<BB, 512>>>(g5, b5);
    k_embed<<<BB, 128>>>(we, out);
}